// round 5
// baseline (speedup 1.0000x reference)
#include <cuda_runtime.h>
#include <cstdint>

#define GN 262144   // 64*64*64 spatial
#define CC 256      // Cin = Cout = R

// Scratch buffers (allocation-free rule: __device__ globals)
__device__ float g_y [(size_t)CC * GN];
__device__ float g_y2[(size_t)CC * GN];

#define APW 136   // As2 pitch in uint2 (128 m + pad)
#define BPW 72    // Bs2 pitch in uint2 (64 n + pad)

// Pack two f32 -> bf16x2 word
__device__ __forceinline__ uint32_t pack_bf16x2(float f_hi, float f_lo) {
    uint32_t d;
    asm("cvt.rn.bf16x2.f32 %0, %1, %2;" : "=r"(d) : "f"(f_hi), "f"(f_lo));
    return d;
}

// Split (f0,f1) into bf16 hi-pair and lo-pair (double-bf16 decomposition)
__device__ __forceinline__ uint2 split2(float f0, float f1) {
    uint32_t h = pack_bf16x2(f1, f0);
    float h0 = __uint_as_float(h << 16);
    float h1 = __uint_as_float(h & 0xFFFF0000u);
    uint32_t l = pack_bf16x2(f1 - h1, f0 - h0);
    return make_uint2(h, l);
}

// ---------------------------------------------------------------------------
// bf16-split tensor-core GEMM (3-term, fp32-accurate to ~2^-18).
// Y[m, n] = sum_k A[k*256 + m] * X[k*GN + n]  (+ bias[m] if BIAS)
// Tiles: BM=128, BN=64, BK=32. 256 threads = 8 warps (2m x 4n), warp = 64x16.
// smem: interleaved {hi,lo} bf16x2 pairs, [kw][m] layout, kw = k/2.
// ---------------------------------------------------------------------------
template<bool BIAS>
__global__ __launch_bounds__(256, 3) void gemm_bf16x2_kernel(
    const float* __restrict__ A,
    const float* __restrict__ X,
    float* __restrict__ Y,
    const float* __restrict__ bias)
{
    __shared__ uint2 As2[16 * APW];   // 17.4 KB
    __shared__ uint2 Bs2[16 * BPW];   //  9.2 KB

    const int tid  = threadIdx.x;
    const int lane = tid & 31;
    const int warp = tid >> 5;
    const int n0 = blockIdx.x * 64;
    const int m0 = blockIdx.y * 128;
    const int wm = (warp & 1) * 64;      // warp m-offset
    const int wn = (warp >> 1) * 16;     // warp n-offset
    const int g  = lane >> 2;            // 0..7
    const int tg = lane & 3;             // 0..3

    // Fill-phase coordinates
    const int fkw = tid >> 4;            // 0..15 (pair-row)
    const int fm8 = (tid & 15) << 3;     // 0..120
    const int fn4 = (tid & 15) << 2;     // 0..60

    float c[4][2][4];
#pragma unroll
    for (int mt = 0; mt < 4; mt++)
#pragma unroll
        for (int nt = 0; nt < 2; nt++)
#pragma unroll
            for (int i = 0; i < 4; i++) c[mt][nt][i] = 0.f;

    // Prefetch tile 0
    float4 ra[4], rb[2];
    {
        const float* pa = &A[(2 * fkw) * 256 + m0 + fm8];
        ra[0] = *(const float4*)(pa);
        ra[1] = *(const float4*)(pa + 4);
        ra[2] = *(const float4*)(pa + 256);
        ra[3] = *(const float4*)(pa + 260);
        const float* pb = &X[(size_t)(2 * fkw) * GN + n0 + fn4];
        rb[0] = *(const float4*)(pb);
        rb[1] = *(const float4*)(pb + GN);
    }

    for (int kt = 0; kt < 256; kt += 32) {
        // Convert + store current tile to smem
        {
            uint2* pa = &As2[fkw * APW + fm8];
            const float* f0 = (const float*)&ra[0];   // row 2kw   (8 floats)
            const float* f1 = (const float*)&ra[2];   // row 2kw+1 (8 floats)
#pragma unroll
            for (int j = 0; j < 8; j++)
                pa[j] = split2(f0[j], f1[j]);
            uint2* pb2 = &Bs2[fkw * BPW + fn4];
            const float* g0 = (const float*)&rb[0];
            const float* g1 = (const float*)&rb[1];
#pragma unroll
            for (int j = 0; j < 4; j++)
                pb2[j] = split2(g0[j], g1[j]);
        }
        __syncthreads();

        // Prefetch next tile (latency hidden under the mma loop).
        // Last iteration re-reads tile 0 (valid memory, values unused).
        {
            int ktn = (kt + 32) & 255;
            const float* pa = &A[(ktn + 2 * fkw) * 256 + m0 + fm8];
            ra[0] = *(const float4*)(pa);
            ra[1] = *(const float4*)(pa + 4);
            ra[2] = *(const float4*)(pa + 256);
            ra[3] = *(const float4*)(pa + 260);
            const float* pb = &X[(size_t)(ktn + 2 * fkw) * GN + n0 + fn4];
            rb[0] = *(const float4*)(pb);
            rb[1] = *(const float4*)(pb + GN);
        }

#pragma unroll
        for (int s = 0; s < 2; s++) {        // two k16 steps
            const int kwb = s * 8;
            // B fragments (hi/lo interleaved in one LDS.64 each)
            uint32_t bhi[2][2], blo[2][2];
#pragma unroll
            for (int nt = 0; nt < 2; nt++) {
                int n = wn + nt * 8 + g;
                uint2 v0 = Bs2[(kwb + tg) * BPW + n];
                uint2 v1 = Bs2[(kwb + tg + 4) * BPW + n];
                bhi[nt][0] = v0.x; blo[nt][0] = v0.y;
                bhi[nt][1] = v1.x; blo[nt][1] = v1.y;
            }
#pragma unroll
            for (int mt = 0; mt < 4; mt++) {
                int m = wm + mt * 16 + g;
                uint2 v0 = As2[(kwb + tg) * APW + m];
                uint2 v1 = As2[(kwb + tg) * APW + m + 8];
                uint2 v2 = As2[(kwb + tg + 4) * APW + m];
                uint2 v3 = As2[(kwb + tg + 4) * APW + m + 8];
                uint32_t ahi[4] = {v0.x, v1.x, v2.x, v3.x};
                uint32_t alo[4] = {v0.y, v1.y, v2.y, v3.y};
#pragma unroll
                for (int nt = 0; nt < 2; nt++) {
#define MMA_BF16(CF, AF, BF)                                                   \
    asm volatile(                                                              \
        "mma.sync.aligned.m16n8k16.row.col.f32.bf16.bf16.f32 "                 \
        "{%0,%1,%2,%3}, {%4,%5,%6,%7}, {%8,%9}, {%0,%1,%2,%3};\n"              \
        : "+f"(CF[0]), "+f"(CF[1]), "+f"(CF[2]), "+f"(CF[3])                   \
        : "r"(AF[0]), "r"(AF[1]), "r"(AF[2]), "r"(AF[3]),                      \
          "r"(BF[0]), "r"(BF[1]))
                    MMA_BF16(c[mt][nt], ahi, bhi[nt]);
                    MMA_BF16(c[mt][nt], ahi, blo[nt]);
                    MMA_BF16(c[mt][nt], alo, bhi[nt]);
                }
            }
        }
        __syncthreads();
    }

    // Epilogue: c0/c1 -> row g, c2/c3 -> row g+8; cols tg*2, tg*2+1
#pragma unroll
    for (int mt = 0; mt < 4; mt++) {
#pragma unroll
        for (int half = 0; half < 2; half++) {
            int m = m0 + wm + mt * 16 + g + half * 8;
            float bv = BIAS ? bias[m] : 0.f;
#pragma unroll
            for (int nt = 0; nt < 2; nt++) {
                float2 o;
                o.x = c[mt][nt][half * 2 + 0] + bv;
                o.y = c[mt][nt][half * 2 + 1] + bv;
                *(float2*)&Y[(size_t)m * GN + n0 + wn + nt * 8 + tg * 2] = o;
            }
        }
    }
}

// ---------------------------------------------------------------------------
// Fused separable 3D conv (3 taps per axis, zero pad 1, stride 1), per rank r.
// Block: one r, one 8x8 (h,w) tile, full d=64 line.
// ---------------------------------------------------------------------------
__global__ __launch_bounds__(256) void conv3_kernel(
    const float* __restrict__ Yin,
    float* __restrict__ Z,
    const float* __restrict__ Ukh,
    const float* __restrict__ Ukw,
    const float* __restrict__ Ukd)
{
    __shared__ float s[6500];    // [hh 0..9][ww 0..9][d 0..63], pitch 65
    __shared__ float s2[4160];   // [hw 0..63][d 0..63], pitch 65

    const int r  = blockIdx.y;
    const int h0 = (blockIdx.x >> 3) * 8 - 1;
    const int w0 = (blockIdx.x & 7) * 8 - 1;

    const float* src = Yin + (size_t)r * GN;

    for (int i = threadIdx.x; i < 6400; i += 256) {
        int d  = i & 63;
        int hw = i >> 6;
        int hh = hw / 10;
        int ww = hw - hh * 10;
        int h = h0 + hh, w = w0 + ww;
        float v = 0.f;
        if ((unsigned)h < 64u && (unsigned)w < 64u)
            v = src[(h << 12) + (w << 6) + d];
        s[hw * 65 + d] = v;
    }

    const float ch0 = Ukh[r], ch1 = Ukh[256 + r], ch2 = Ukh[512 + r];
    const float cw0 = Ukw[r], cw1 = Ukw[256 + r], cw2 = Ukw[512 + r];
    const float cd0 = Ukd[r], cd1 = Ukd[256 + r], cd2 = Ukd[512 + r];

    __syncthreads();

    const int q  = threadIdx.x >> 6;
    const int rc = threadIdx.x & 63;
    const int oh = rc >> 3;
    const int ow = rc & 7;

    const float* p0 = &s[(oh * 10 + ow) * 65];

    float tmp[18];
    const int dbase = q * 16 - 1;
#pragma unroll
    for (int j = 0; j < 18; j++) {
        int d = dbase + j;
        float v = 0.f;
        if ((unsigned)d < 64u) {
            const float* p = p0 + d;
            v = ch0 * (cw0 * p[0]    + cw1 * p[65]   + cw2 * p[130])
              + ch1 * (cw0 * p[650]  + cw1 * p[715]  + cw2 * p[780])
              + ch2 * (cw0 * p[1300] + cw1 * p[1365] + cw2 * p[1430]);
        }
        tmp[j] = v;
    }

    float* st = &s2[rc * 65 + q * 16];
#pragma unroll
    for (int j = 0; j < 16; j++)
        st[j] = cd0 * tmp[j] + cd1 * tmp[j + 1] + cd2 * tmp[j + 2];

    __syncthreads();

    float* dst = Z + (size_t)r * GN;
    const int hb = h0 + 1, wb = w0 + 1;
    for (int i = threadIdx.x; i < 4096; i += 256) {
        int d  = i & 63;
        int hw = i >> 6;
        int ohh = hw >> 3;
        int oww = hw & 7;
        dst[((hb + ohh) << 12) + ((wb + oww) << 6) + d] = s2[hw * 65 + d];
    }
}

// ---------------------------------------------------------------------------
extern "C" void kernel_launch(void* const* d_in, const int* in_sizes, int n_in,
                              void* d_out, int out_size)
{
    const float* x      = (const float*)d_in[0];
    const float* U_kh   = (const float*)d_in[1];
    const float* U_kw   = (const float*)d_in[2];
    const float* U_kd   = (const float*)d_in[3];
    const float* U_cin  = (const float*)d_in[4];
    const float* U_cout = (const float*)d_in[5];
    const float* bias   = (const float*)d_in[6];
    float* out = (float*)d_out;

    float *y, *y2;
    cudaGetSymbolAddress((void**)&y,  g_y);
    cudaGetSymbolAddress((void**)&y2, g_y2);

    dim3 ggrid(GN / 64, 2);   // 4096 x 2 blocks

    // Stage 1: y[r, s] = sum_c U_cin[c, r] * x[c, s]
    gemm_bf16x2_kernel<false><<<ggrid, 256>>>(U_cin, x, y, nullptr);

    // Stage 2: fused separable 3x3x3 conv per rank
    conv3_kernel<<<dim3(64, 256), 256>>>(y, y2, U_kh, U_kw, U_kd);

    // Stage 3: out[co, s] = sum_r U_cout[r, co] * y2[r, s] + bias[co]
    gemm_bf16x2_kernel<true><<<ggrid, 256>>>(U_cout, y2, out, bias);
}